// round 13
// baseline (speedup 1.0000x reference)
#include <cuda_runtime.h>
#include <cuda_bf16.h>
#include <cuda_fp16.h>
#include <cstdint>
#include <math.h>

// ----------------------------------------------------------------------------
// B=128, T=2048, H=128
//   z = tanh(Hp @ Wh^T + Hd @ Wd^T); energy = z @ Wa + ba
//   alpha = softmax_T(energy * (1 + softplus(beta)*acc_w/max(acc_w)))
//   context = sum_t alpha * Hp
// Output: [context (B*H) | alpha (B*T)] fp32
//
// sm_103 (non-'a') ptxas: tcgen05 unavailable -> legacy mma.sync (HMMA).
// Single-term fp16 MMA, fp32 accum. 512 threads / 16 warps (4 per SMSP) in a
// 4x4 warp grid for HMMA latency hiding; convert+prefetch overlapped with MMA
// via per-thread-partitioned stage buffer (no barriers on stage).
// ----------------------------------------------------------------------------

static constexpr int Bsz = 128, Tlen = 2048, Hdim = 128;
static constexpr int NTILES = Bsz * Tlen / 128;   // 2048 tiles of 128 tokens
static constexpr int GRID1  = 152;                // persistent CTAs (GB300 SMs)
static constexpr int THR1   = 512;                // 16 warps

__device__ float g_energy[Bsz * Tlen];
__device__ float g_ctx_part[Bsz * 8 * Hdim];      // context partials

// ---------------------------- helpers ---------------------------------------
__device__ __forceinline__ uint32_t smem_u32(const void* p) {
    uint32_t a;
    asm("{ .reg .u64 t; cvta.to.shared.u64 t, %1; cvt.u32.u64 %0, t; }"
        : "=r"(a) : "l"(p));
    return a;
}

__device__ __forceinline__ void ldsm_x4(uint32_t* r, uint32_t addr) {
    asm volatile("ldmatrix.sync.aligned.m8n8.x4.shared.b16 {%0,%1,%2,%3}, [%4];"
                 : "=r"(r[0]), "=r"(r[1]), "=r"(r[2]), "=r"(r[3]) : "r"(addr));
}

__device__ __forceinline__ void mma16816(float* d, const uint32_t* a,
                                         uint32_t b0, uint32_t b1) {
    asm volatile("mma.sync.aligned.m16n8k16.row.col.f32.f16.f16.f32 "
                 "{%0,%1,%2,%3}, {%4,%5,%6,%7}, {%8,%9}, {%0,%1,%2,%3};"
                 : "+f"(d[0]), "+f"(d[1]), "+f"(d[2]), "+f"(d[3])
                 : "r"(a[0]), "r"(a[1]), "r"(a[2]), "r"(a[3]), "r"(b0), "r"(b1));
}

__device__ __forceinline__ float tanh_approx(float x) {
    float y;
    asm("tanh.approx.f32 %0, %1;" : "=f"(y) : "f"(x));
    return y;
}

__device__ __forceinline__ void cp_async16(uint32_t saddr, const void* g) {
    asm volatile("cp.async.cg.shared.global [%0], [%1], 16;"
                 :: "r"(saddr), "l"(g) : "memory");
}
#define CP_COMMIT() asm volatile("cp.async.commit_group;" ::: "memory")
#define CP_WAIT0()  asm volatile("cp.async.wait_group 0;" ::: "memory")

// ---------------------------- SMEM layout -----------------------------------
// fp16 tiles: 128 rows x 136 halves (pitch 272 B -> 4-bank row rotation,
// conflict-free ldmatrix).
static constexpr int PITCH_B  = 272;
static constexpr int TILE_B   = 128 * PITCH_B;       // 34816 B
static constexpr int SM_AH0   = 0;                   // Hp tile (fp16)
static constexpr int SM_AH1   = SM_AH0 + TILE_B;     // Hd tile (fp16)
static constexpr int SM_WH    = SM_AH1 + TILE_B;     // Wh (fp16)
static constexpr int SM_WD    = SM_WH + TILE_B;      // Wd (fp16)
static constexpr int SM_STAGE = SM_WD + TILE_B;      // raw fp32 128x128 (thread-partitioned)
static constexpr int SM_WA    = SM_STAGE + 65536;    // 204800
static constexpr int SM_PART  = SM_WA + 512;         // 205312: 4x128 fp32
static constexpr int SMEM1    = SM_PART + 2048;      // 207360 B

// Each thread owns 8 float4s of the stage: fi = wid*256 + k*32 + lane, k=0..7.
// The SAME thread cp.asyncs, converts, and re-prefetches those fi -> no barrier
// needed on the stage buffer (per-thread cp.async.wait orders it).

__device__ __forceinline__ void prefetch_own(uint32_t sb, const float* __restrict__ src,
                                             int fbase) {
    #pragma unroll
    for (int k = 0; k < 8; k++) {
        int fi = fbase + k * 32;
        cp_async16(sb + SM_STAGE + (uint32_t)fi * 16, src + (size_t)fi * 4);
    }
    CP_COMMIT();
}

__device__ __forceinline__ void convert_one(char* smem, int dst, int fi,
                                            const float4* stg) {
    float4 v = stg[fi];
    int row = fi >> 5, c = fi & 31;
    __half2 h0 = __floats2half2_rn(v.x, v.y);
    __half2 h1 = __floats2half2_rn(v.z, v.w);
    *(uint2*)(smem + dst + (uint32_t)row * PITCH_B + (uint32_t)c * 8) =
        make_uint2(*(const uint32_t*)&h0, *(const uint32_t*)&h1);
}

// One GEMM pass: D += AH(aBase) @ W(wBase)^T, interleaved with (optional)
// convert of the stage into cvtDst and (optional) prefetch of pf into stage.
// Warp grid 4(M) x 4(N): warp = rows 32*wm..+31 (2 m-tiles), cols 32*wn..+31.
template <bool CVT, bool PF>
__device__ __forceinline__ void pass_ic(char* smem, uint32_t sb,
                                        uint32_t aBase, uint32_t wBase, int cvtDst,
                                        const float* __restrict__ pf, int fbase,
                                        int lane, int wm, int wn, float d[2][4][4]) {
    uint32_t arow = (uint32_t)(wm * 32 + (lane & 15));
    uint32_t acol = (uint32_t)((lane >> 4) * 8);
    uint32_t brow = (uint32_t)(wn * 32 + (lane & 7));
    uint32_t bcol = (uint32_t)((lane >> 3) * 8);
    const float4* stg = (const float4*)(smem + SM_STAGE);
    #pragma unroll
    for (int k2 = 0; k2 < 4; k2++) {
        uint32_t k0 = (uint32_t)(k2 * 32);
        uint32_t a[2][2][4];
        #pragma unroll
        for (int mt = 0; mt < 2; mt++)
            #pragma unroll
            for (int ks = 0; ks < 2; ks++)
                ldsm_x4(a[mt][ks],
                        aBase + (arow + mt * 16) * PITCH_B
                              + (k0 + ks * 16 + acol) * 2);
        #pragma unroll
        for (int nt = 0; nt < 4; nt++) {
            uint32_t b[4];
            ldsm_x4(b, wBase + (brow + nt * 8) * PITCH_B + (k0 + bcol) * 2);
            mma16816(d[0][nt], a[0][0], b[0], b[1]);
            mma16816(d[0][nt], a[0][1], b[2], b[3]);
            mma16816(d[1][nt], a[1][0], b[0], b[1]);
            mma16816(d[1][nt], a[1][1], b[2], b[3]);
        }
        if (CVT) {
            if (k2 == 0) CP_WAIT0();    // this thread's staged rows have landed
            #pragma unroll
            for (int j = 0; j < 2; j++)
                convert_one(smem, cvtDst, fbase + (k2 * 2 + j) * 32, stg);
        }
    }
    if (PF) prefetch_own(sb, pf, fbase);
}

__global__ void __launch_bounds__(THR1, 1)
energy_kernel(const float* __restrict__ Hp, const float* __restrict__ Hd,
              const float* __restrict__ Wh, const float* __restrict__ Wd,
              const float* __restrict__ Wa, const float* __restrict__ ba_ptr) {
    extern __shared__ char smem[];
    uint32_t sb = smem_u32(smem);
    const int tid = threadIdx.x;
    const int wid = tid >> 5, lane = tid & 31;
    const int wm  = wid >> 2, wn = wid & 3;
    const int g   = lane >> 2, t = lane & 3;
    const int fbase = wid * 256 + lane;

    // one-time: weights fp32 -> fp16 tiles
    for (int idx = tid; idx < 8192; idx += THR1) {
        int o = idx >> 6, h = (idx & 63) * 2;
        uint32_t off = (uint32_t)o * PITCH_B + (uint32_t)h * 2;
        float2 a = *(const float2*)(Wh + o * 128 + h);
        float2 b = *(const float2*)(Wd + o * 128 + h);
        __half2 ah = __floats2half2_rn(a.x, a.y);
        __half2 bh = __floats2half2_rn(b.x, b.y);
        *(uint32_t*)(smem + SM_WH + off) = *(const uint32_t*)&ah;
        *(uint32_t*)(smem + SM_WD + off) = *(const uint32_t*)&bh;
    }
    if (tid < 128) ((float*)(smem + SM_WA))[tid] = Wa[tid];
    const float ba = ba_ptr[0];
    float* sPart = (float*)(smem + SM_PART);
    const float* sWa = (const float*)(smem + SM_WA);

    // prologue: stage <- Hp[tile0]; convert -> AH0; stage <- Hd[tile0] in flight
    const int tile0 = blockIdx.x;
    {
        const float4* stg = (const float4*)(smem + SM_STAGE);
        prefetch_own(sb, Hp + (size_t)tile0 * 16384, fbase);
        CP_WAIT0();
        #pragma unroll
        for (int k = 0; k < 8; k++)
            convert_one(smem, SM_AH0, fbase + k * 32, stg);
        prefetch_own(sb, Hd + (size_t)tile0 * 16384, fbase);
    }
    __syncthreads();   // weights + AH0 visible to all warps

    for (int tile = tile0; tile < NTILES; tile += GRID1) {
        size_t nbase = (size_t)(tile + GRID1) * 16384;
        const bool hasNext = (tile + GRID1) < NTILES;

        float d[2][4][4];
        #pragma unroll
        for (int mt = 0; mt < 2; mt++)
            #pragma unroll
            for (int nt = 0; nt < 4; nt++)
                #pragma unroll
                for (int j = 0; j < 4; j++) d[mt][nt][j] = 0.f;

        // pass 1: MMA(Hp_i @ Wh) | convert Hd_i -> AH1 | prefetch Hp_{i+1}
        if (hasNext)
            pass_ic<true, true>(smem, sb, sb + SM_AH0, sb + SM_WH, SM_AH1,
                                Hp + nbase, fbase, lane, wm, wn, d);
        else
            pass_ic<true, false>(smem, sb, sb + SM_AH0, sb + SM_WH, SM_AH1,
                                 nullptr, fbase, lane, wm, wn, d);
        __syncthreads();   // AH1 complete before pass 2 reads it

        // pass 2: MMA(Hd_i @ Wd) | convert Hp_{i+1} -> AH0 | prefetch Hd_{i+1}
        if (hasNext)
            pass_ic<true, true>(smem, sb, sb + SM_AH1, sb + SM_WD, SM_AH0,
                                Hd + nbase, fbase, lane, wm, wn, d);
        else
            pass_ic<false, false>(smem, sb, sb + SM_AH1, sb + SM_WD, SM_AH0,
                                  nullptr, fbase, lane, wm, wn, d);

        // epilogue: energy[token] = ba + sum_o Wa[o]*tanh(D[token][o])
        float e[2][2] = {{0.f, 0.f}, {0.f, 0.f}};
        #pragma unroll
        for (int nt = 0; nt < 4; nt++) {
            int n = wn * 32 + nt * 8 + 2 * t;
            float wa0 = sWa[n], wa1 = sWa[n + 1];
            #pragma unroll
            for (int mt = 0; mt < 2; mt++) {
                e[mt][0] += wa0 * tanh_approx(d[mt][nt][0])
                          + wa1 * tanh_approx(d[mt][nt][1]);
                e[mt][1] += wa0 * tanh_approx(d[mt][nt][2])
                          + wa1 * tanh_approx(d[mt][nt][3]);
            }
        }
        #pragma unroll
        for (int mt = 0; mt < 2; mt++)
            #pragma unroll
            for (int r = 0; r < 2; r++) {
                e[mt][r] += __shfl_xor_sync(0xFFFFFFFFu, e[mt][r], 1);
                e[mt][r] += __shfl_xor_sync(0xFFFFFFFFu, e[mt][r], 2);
            }
        if (t == 0) {
            #pragma unroll
            for (int mt = 0; mt < 2; mt++) {
                int row = wm * 32 + mt * 16 + g;
                sPart[wn * 128 + row]     = e[mt][0];
                sPart[wn * 128 + row + 8] = e[mt][1];
            }
        }
        __syncthreads();   // sPart ready; also AH0 (next Hp) visible for pass 1
        if (tid < 128)
            g_energy[(size_t)tile * 128 + tid] =
                sPart[tid] + sPart[128 + tid] + sPart[256 + tid] + sPart[384 + tid] + ba;
        __syncthreads();   // sPart free before next tile's epilogue reuse
    }
}

// ---------------------------- Kernel 2: softmax -> alpha --------------------
__global__ void __launch_bounds__(256)
softmax_kernel(const float* __restrict__ accw, const float* __restrict__ beta_ptr,
               float* __restrict__ out) {
    __shared__ float s_e[2048];
    __shared__ float s_red[256];
    int b = blockIdx.x, tid = threadIdx.x;
    const float* aw = accw + (size_t)b * Tlen;
    const float* en = g_energy + (size_t)b * Tlen;

    float lm = -INFINITY;
    for (int t = tid; t < Tlen; t += 256) lm = fmaxf(lm, aw[t]);
    s_red[tid] = lm; __syncthreads();
    for (int s = 128; s > 0; s >>= 1) {
        if (tid < s) s_red[tid] = fmaxf(s_red[tid], s_red[tid + s]);
        __syncthreads();
    }
    float denom = fmaxf(s_red[0], 1e-6f);
    __syncthreads();

    float bet = beta_ptr[0];
    float bp = (bet > 20.f) ? bet : log1pf(expf(bet));

    lm = -INFINITY;
    for (int t = tid; t < Tlen; t += 256) {
        float e = en[t] * (1.f + bp * (aw[t] / denom));
        s_e[t] = e;
        lm = fmaxf(lm, e);
    }
    s_red[tid] = lm; __syncthreads();
    for (int s = 128; s > 0; s >>= 1) {
        if (tid < s) s_red[tid] = fmaxf(s_red[tid], s_red[tid + s]);
        __syncthreads();
    }
    float m = s_red[0];
    __syncthreads();

    float ls = 0.f;
    for (int t = tid; t < Tlen; t += 256) {
        float ex = expf(s_e[t] - m);
        s_e[t] = ex;
        ls += ex;
    }
    s_red[tid] = ls; __syncthreads();
    for (int s = 128; s > 0; s >>= 1) {
        if (tid < s) s_red[tid] += s_red[tid + s];
        __syncthreads();
    }
    float inv = 1.f / s_red[0];
    __syncthreads();

    float* alpha_out = out + Bsz * Hdim + (size_t)b * Tlen;
    for (int t = tid; t < Tlen; t += 256)
        alpha_out[t] = s_e[t] * inv;
}

// -------------------- Kernel 3: context partials (1024 CTAs) ----------------
__global__ void __launch_bounds__(256)
context_partial_kernel(const float* __restrict__ Hp, const float* __restrict__ out) {
    __shared__ float s_a[256];
    __shared__ float s_ctx[8 * 128];
    int b = blockIdx.x >> 3, chunk = blockIdx.x & 7;
    int tid = threadIdx.x, w = tid >> 5, lane = tid & 31;

    const float* alpha = out + Bsz * Hdim + (size_t)b * Tlen + chunk * 256;
    s_a[tid] = alpha[tid];
    __syncthreads();

    const float4* hp = (const float4*)(Hp + ((size_t)b * Tlen + chunk * 256) * Hdim);
    float4 acc = {0.f, 0.f, 0.f, 0.f};
    #pragma unroll 4
    for (int t = w; t < 256; t += 8) {
        float a = s_a[t];
        float4 v = hp[t * 32 + lane];
        acc.x += a * v.x; acc.y += a * v.y; acc.z += a * v.z; acc.w += a * v.w;
    }
    s_ctx[w * 128 + lane * 4 + 0] = acc.x;
    s_ctx[w * 128 + lane * 4 + 1] = acc.y;
    s_ctx[w * 128 + lane * 4 + 2] = acc.z;
    s_ctx[w * 128 + lane * 4 + 3] = acc.w;
    __syncthreads();
    if (tid < 128) {
        float c = 0.f;
        #pragma unroll
        for (int ww = 0; ww < 8; ww++) c += s_ctx[ww * 128 + tid];
        g_ctx_part[(size_t)blockIdx.x * 128 + tid] = c;
    }
}

// -------------------- Kernel 4: reduce 8 partials per batch -----------------
__global__ void __launch_bounds__(128)
context_reduce_kernel(float* __restrict__ out) {
    int b = blockIdx.x, tid = threadIdx.x;
    float c = 0.f;
    #pragma unroll
    for (int k = 0; k < 8; k++)
        c += g_ctx_part[((size_t)b * 8 + k) * 128 + tid];
    out[(size_t)b * Hdim + tid] = c;
}

// ---------------------------- launcher --------------------------------------
extern "C" void kernel_launch(void* const* d_in, const int* in_sizes, int n_in,
                              void* d_out, int out_size) {
    (void)in_sizes; (void)n_in; (void)out_size;
    const float* Hp   = (const float*)d_in[0];
    const float* Hd   = (const float*)d_in[1];
    const float* accw = (const float*)d_in[2];
    const float* Wh   = (const float*)d_in[3];
    const float* Wd   = (const float*)d_in[4];
    const float* Wa   = (const float*)d_in[5];
    const float* ba   = (const float*)d_in[6];
    const float* beta = (const float*)d_in[7];
    float* out = (float*)d_out;

    cudaFuncSetAttribute(energy_kernel, cudaFuncAttributeMaxDynamicSharedMemorySize, SMEM1);
    energy_kernel<<<GRID1, THR1, SMEM1>>>(Hp, Hd, Wh, Wd, Wa, ba);
    softmax_kernel<<<Bsz, 256>>>(accw, beta, out);
    context_partial_kernel<<<Bsz * 8, 256>>>(Hp, out);
    context_reduce_kernel<<<Bsz, 128>>>(out);
}

// round 14
// speedup vs baseline: 1.0604x; 1.0604x over previous
#include <cuda_runtime.h>
#include <cuda_bf16.h>
#include <cuda_fp16.h>
#include <cstdint>
#include <math.h>

// ----------------------------------------------------------------------------
// B=128, T=2048, H=128
//   z = tanh(Hp @ Wh^T + Hd @ Wd^T); energy = z @ Wa + ba
//   alpha = softmax_T(energy * (1 + softplus(beta)*acc_w/max(acc_w)))
//   context = sum_t alpha * Hp
// Output: [context (B*H) | alpha (B*T)] fp32
//
// sm_103 (non-'a') ptxas: tcgen05 unavailable -> legacy mma.sync (HMMA).
// Single-term fp16 MMA, fp32 accum. Context fused into the energy epilogue:
//   w_t = exp(scaled energy) (bounded, no max-sub needed);
//   per-tile C[h] = sum_t w_t*Hp[t][h] via one M16 MMA with trans-ldmatrix B;
//   finalize kernel divides by Z per batch. Eliminates the 134MB Hp re-read.
// ----------------------------------------------------------------------------

static constexpr int Bsz = 128, Tlen = 2048, Hdim = 128;
static constexpr int NTILES = Bsz * Tlen / 128;   // 2048 tiles of 128 tokens
static constexpr int GRID1  = 152;                // persistent CTAs (GB300 SMs)
static constexpr int THR1   = 512;                // 16 warps

__device__ float g_expE[Bsz * Tlen];              // exp(scaled energy)
__device__ float g_S1[NTILES];                    // per-tile sum of exp
__device__ float g_ctx_part[NTILES * Hdim];       // per-tile exp-weighted Hp sums
__device__ float g_invmax[Bsz];                   // 1/clip(max(acc_w),1e-6)
__device__ float g_bp[1];                         // softplus(beta)

// ---------------------------- helpers ---------------------------------------
__device__ __forceinline__ uint32_t smem_u32(const void* p) {
    uint32_t a;
    asm("{ .reg .u64 t; cvta.to.shared.u64 t, %1; cvt.u32.u64 %0, t; }"
        : "=r"(a) : "l"(p));
    return a;
}

__device__ __forceinline__ void ldsm_x4(uint32_t* r, uint32_t addr) {
    asm volatile("ldmatrix.sync.aligned.m8n8.x4.shared.b16 {%0,%1,%2,%3}, [%4];"
                 : "=r"(r[0]), "=r"(r[1]), "=r"(r[2]), "=r"(r[3]) : "r"(addr));
}

__device__ __forceinline__ void ldsm_x2_trans(uint32_t* r, uint32_t addr) {
    asm volatile("ldmatrix.sync.aligned.m8n8.x2.trans.shared.b16 {%0,%1}, [%2];"
                 : "=r"(r[0]), "=r"(r[1]) : "r"(addr));
}

__device__ __forceinline__ void mma16816(float* d, const uint32_t* a,
                                         uint32_t b0, uint32_t b1) {
    asm volatile("mma.sync.aligned.m16n8k16.row.col.f32.f16.f16.f32 "
                 "{%0,%1,%2,%3}, {%4,%5,%6,%7}, {%8,%9}, {%0,%1,%2,%3};"
                 : "+f"(d[0]), "+f"(d[1]), "+f"(d[2]), "+f"(d[3])
                 : "r"(a[0]), "r"(a[1]), "r"(a[2]), "r"(a[3]), "r"(b0), "r"(b1));
}

__device__ __forceinline__ float tanh_approx(float x) {
    float y;
    asm("tanh.approx.f32 %0, %1;" : "=f"(y) : "f"(x));
    return y;
}

__device__ __forceinline__ void cp_async16(uint32_t saddr, const void* g) {
    asm volatile("cp.async.cg.shared.global [%0], [%1], 16;"
                 :: "r"(saddr), "l"(g) : "memory");
}
#define CP_COMMIT() asm volatile("cp.async.commit_group;" ::: "memory")
#define CP_WAIT0()  asm volatile("cp.async.wait_group 0;" ::: "memory")

// ---------------------------- SMEM layout -----------------------------------
static constexpr int PITCH_B  = 272;                 // 4-bank rotation per row
static constexpr int TILE_B   = 128 * PITCH_B;       // 34816 B
static constexpr int SM_AH0   = 0;                   // Hp tile (fp16)
static constexpr int SM_AH1   = SM_AH0 + TILE_B;     // Hd tile (fp16)
static constexpr int SM_WH    = SM_AH1 + TILE_B;     // Wh (fp16)
static constexpr int SM_WD    = SM_WH + TILE_B;      // Wd (fp16)
static constexpr int SM_STAGE = SM_WD + TILE_B;      // raw fp32 128x128
static constexpr int SM_WA    = SM_STAGE + 65536;    // 204800: Wa 128 fp32
static constexpr int SM_PART  = SM_WA + 512;         // 205312: 4x128 fp32
static constexpr int SM_EXPA  = SM_PART + 2048;      // 207360: 16x136 fp16 A strip
static constexpr int SM_RED   = SM_EXPA + 16 * PITCH_B;  // 211712: 4 fp32
static constexpr int SMEM1    = SM_RED + 64;         // 211776 B

// Each thread owns 8 float4s of the stage: fi = wid*256 + k*32 + lane, k=0..7.
__device__ __forceinline__ void prefetch_own(uint32_t sb, const float* __restrict__ src,
                                             int fbase) {
    #pragma unroll
    for (int k = 0; k < 8; k++) {
        int fi = fbase + k * 32;
        cp_async16(sb + SM_STAGE + (uint32_t)fi * 16, src + (size_t)fi * 4);
    }
    CP_COMMIT();
}

__device__ __forceinline__ void convert_one(char* smem, int dst, int fi,
                                            const float4* stg) {
    float4 v = stg[fi];
    int row = fi >> 5, c = fi & 31;
    __half2 h0 = __floats2half2_rn(v.x, v.y);
    __half2 h1 = __floats2half2_rn(v.z, v.w);
    *(uint2*)(smem + dst + (uint32_t)row * PITCH_B + (uint32_t)c * 8) =
        make_uint2(*(const uint32_t*)&h0, *(const uint32_t*)&h1);
}

// One GEMM pass: D += AH(aBase) @ W(wBase)^T. Optionally convert the stage
// into cvtDst (starting at k2==CVT_START) and prefetch pf into the stage.
template <bool CVT, bool PF, int CVT_START>
__device__ __forceinline__ void pass_ic(char* smem, uint32_t sb,
                                        uint32_t aBase, uint32_t wBase, int cvtDst,
                                        const float* __restrict__ pf, int fbase,
                                        int lane, int wm, int wn, float d[2][4][4]) {
    uint32_t arow = (uint32_t)(wm * 32 + (lane & 15));
    uint32_t acol = (uint32_t)((lane >> 4) * 8);
    uint32_t brow = (uint32_t)(wn * 32 + (lane & 7));
    uint32_t bcol = (uint32_t)((lane >> 3) * 8);
    const float4* stg = (const float4*)(smem + SM_STAGE);
    constexpr int PER = 8 / (4 - CVT_START);   // converts per k2 step
    #pragma unroll
    for (int k2 = 0; k2 < 4; k2++) {
        uint32_t k0 = (uint32_t)(k2 * 32);
        uint32_t a[2][2][4];
        #pragma unroll
        for (int mt = 0; mt < 2; mt++)
            #pragma unroll
            for (int ks = 0; ks < 2; ks++)
                ldsm_x4(a[mt][ks],
                        aBase + (arow + mt * 16) * PITCH_B
                              + (k0 + ks * 16 + acol) * 2);
        #pragma unroll
        for (int nt = 0; nt < 4; nt++) {
            uint32_t b[4];
            ldsm_x4(b, wBase + (brow + nt * 8) * PITCH_B + (k0 + bcol) * 2);
            mma16816(d[0][nt], a[0][0], b[0], b[1]);
            mma16816(d[0][nt], a[0][1], b[2], b[3]);
            mma16816(d[1][nt], a[1][0], b[0], b[1]);
            mma16816(d[1][nt], a[1][1], b[2], b[3]);
        }
        if (CVT && k2 >= CVT_START) {
            if (k2 == CVT_START) CP_WAIT0();
            #pragma unroll
            for (int j = 0; j < PER; j++)
                convert_one(smem, cvtDst, fbase + ((k2 - CVT_START) * PER + j) * 32, stg);
        }
    }
    if (PF) prefetch_own(sb, pf, fbase);
}

__global__ void __launch_bounds__(THR1, 1)
energy_kernel(const float* __restrict__ Hp, const float* __restrict__ Hd,
              const float* __restrict__ accw,
              const float* __restrict__ Wh, const float* __restrict__ Wd,
              const float* __restrict__ Wa, const float* __restrict__ ba_ptr) {
    extern __shared__ char smem[];
    uint32_t sb = smem_u32(smem);
    const int tid = threadIdx.x;
    const int wid = tid >> 5, lane = tid & 31;
    const int wm  = wid >> 2, wn = wid & 3;
    const int g   = lane >> 2, t = lane & 3;
    const int fbase = wid * 256 + lane;

    // one-time: weights fp32 -> fp16 tiles; zero the 16-row exp A strip
    for (int idx = tid; idx < 8192; idx += THR1) {
        int o = idx >> 6, h = (idx & 63) * 2;
        uint32_t off = (uint32_t)o * PITCH_B + (uint32_t)h * 2;
        float2 a = *(const float2*)(Wh + o * 128 + h);
        float2 b = *(const float2*)(Wd + o * 128 + h);
        __half2 ah = __floats2half2_rn(a.x, a.y);
        __half2 bh = __floats2half2_rn(b.x, b.y);
        *(uint32_t*)(smem + SM_WH + off) = *(const uint32_t*)&ah;
        *(uint32_t*)(smem + SM_WD + off) = *(const uint32_t*)&bh;
    }
    for (int idx = tid; idx < 16 * PITCH_B / 4; idx += THR1)
        ((uint32_t*)(smem + SM_EXPA))[idx] = 0;
    if (tid < 128) ((float*)(smem + SM_WA))[tid] = Wa[tid];
    const float ba = ba_ptr[0];
    const float bp = g_bp[0];
    float* sPart = (float*)(smem + SM_PART);
    float* sRed  = (float*)(smem + SM_RED);
    const float* sWa = (const float*)(smem + SM_WA);
    __half* sExpRow = (__half*)(smem + SM_EXPA);   // row 0 of A strip

    // prologue: stage <- Hd[tile0]; convert -> AH1; stage <- Hp[tile0]
    const int tile0 = blockIdx.x;
    {
        const float4* stg = (const float4*)(smem + SM_STAGE);
        prefetch_own(sb, Hd + (size_t)tile0 * 16384, fbase);
        CP_WAIT0();
        #pragma unroll
        for (int k = 0; k < 8; k++)
            convert_one(smem, SM_AH1, fbase + k * 32, stg);
        prefetch_own(sb, Hp + (size_t)tile0 * 16384, fbase);
    }
    __syncthreads();   // weights + AH1 visible

    for (int tile = tile0; tile < NTILES; tile += GRID1) {
        size_t nbase = (size_t)(tile + GRID1) * 16384;
        const bool hasNext = (tile + GRID1) < NTILES;

        float d[2][4][4];
        #pragma unroll
        for (int mt = 0; mt < 2; mt++)
            #pragma unroll
            for (int nt = 0; nt < 4; nt++)
                #pragma unroll
                for (int j = 0; j < 4; j++) d[mt][nt][j] = 0.f;

        // pass 1: MMA(Hd_i @ Wd, A=AH1) | convert Hp_i -> AH0 | prefetch Hd_{i+1}
        if (hasNext)
            pass_ic<true, true, 0>(smem, sb, sb + SM_AH1, sb + SM_WD, SM_AH0,
                                   Hd + nbase, fbase, lane, wm, wn, d);
        else
            pass_ic<true, false, 0>(smem, sb, sb + SM_AH1, sb + SM_WD, SM_AH0,
                                    nullptr, fbase, lane, wm, wn, d);
        __syncthreads();   // AH0 (Hp_i) ready; AH1 reads done

        // pass 2: MMA(Hp_i @ Wh, A=AH0) | convert Hd_{i+1} -> AH1 (late) | pf Hp_{i+1}
        if (hasNext)
            pass_ic<true, true, 2>(smem, sb, sb + SM_AH0, sb + SM_WH, SM_AH1,
                                   Hp + nbase, fbase, lane, wm, wn, d);
        else
            pass_ic<false, false, 2>(smem, sb, sb + SM_AH0, sb + SM_WH, SM_AH1,
                                     nullptr, fbase, lane, wm, wn, d);

        // ---- epilogue part 1: per-token energy -> w = exp(scaled energy) ----
        float e[2][2] = {{0.f, 0.f}, {0.f, 0.f}};
        #pragma unroll
        for (int nt = 0; nt < 4; nt++) {
            int n = wn * 32 + nt * 8 + 2 * t;
            float wa0 = sWa[n], wa1 = sWa[n + 1];
            #pragma unroll
            for (int mt = 0; mt < 2; mt++) {
                e[mt][0] += wa0 * tanh_approx(d[mt][nt][0])
                          + wa1 * tanh_approx(d[mt][nt][1]);
                e[mt][1] += wa0 * tanh_approx(d[mt][nt][2])
                          + wa1 * tanh_approx(d[mt][nt][3]);
            }
        }
        #pragma unroll
        for (int mt = 0; mt < 2; mt++)
            #pragma unroll
            for (int r = 0; r < 2; r++) {
                e[mt][r] += __shfl_xor_sync(0xFFFFFFFFu, e[mt][r], 1);
                e[mt][r] += __shfl_xor_sync(0xFFFFFFFFu, e[mt][r], 2);
            }
        if (t == 0) {
            #pragma unroll
            for (int mt = 0; mt < 2; mt++) {
                int row = wm * 32 + mt * 16 + g;
                sPart[wn * 128 + row]     = e[mt][0];
                sPart[wn * 128 + row + 8] = e[mt][1];
            }
        }
        __syncthreads();   // sPart complete

        if (tid < 128) {
            float et = sPart[tid] + sPart[128 + tid] + sPart[256 + tid]
                     + sPart[384 + tid] + ba;
            float aw = accw[(size_t)tile * 128 + tid];
            int bb = tile >> 4;
            float sc = 1.f + bp * (aw * g_invmax[bb]);
            float w = expf(et * sc);                 // bounded: |arg| < ~6
            g_expE[(size_t)tile * 128 + tid] = w;
            sExpRow[tid] = __float2half_rn(w);
            // per-warp sum of w (4 full warps)
            float s = w;
            #pragma unroll
            for (int o = 16; o > 0; o >>= 1)
                s += __shfl_xor_sync(0xFFFFFFFFu, s, o);
            if (lane == 0) sRed[wid] = s;
        }
        __syncthreads();   // sExpRow + sRed ready
        if (tid == 0)
            g_S1[tile] = sRed[0] + sRed[1] + sRed[2] + sRed[3];

        // ---- epilogue part 2: context partial C[h] = sum_t w_t * Hp[t][h] ----
        {
            float dc[4] = {0.f, 0.f, 0.f, 0.f};
            uint32_t h0 = (uint32_t)(wid * 8);
            #pragma unroll
            for (int kk = 0; kk < 8; kk++) {
                uint32_t areg[4];
                ldsm_x4(areg, sb + SM_EXPA + (uint32_t)(lane & 15) * PITCH_B
                              + (uint32_t)(kk * 16 + (lane >> 4) * 8) * 2);
                uint32_t breg[2];
                ldsm_x2_trans(breg, sb + SM_AH0
                              + (uint32_t)(kk * 16 + (lane & 15)) * PITCH_B + h0 * 2);
                mma16816(dc, areg, breg[0], breg[1]);
            }
            if ((lane >> 2) == 0) {   // row 0 of M16 lives in lanes 0-3 (d0,d1)
                int h = (int)h0 + (lane & 3) * 2;
                g_ctx_part[(size_t)tile * 128 + h]     = dc[0];
                g_ctx_part[(size_t)tile * 128 + h + 1] = dc[1];
            }
        }
        __syncthreads();   // AH0/sExpRow reads done before next pass1 overwrites
    }
}

// -------------------- Kernel 0: acc_w row max + softplus(beta) --------------
__global__ void __launch_bounds__(256)
premax_kernel(const float* __restrict__ accw, const float* __restrict__ beta_ptr) {
    __shared__ float s_red[256];
    int b = blockIdx.x, tid = threadIdx.x;
    const float* aw = accw + (size_t)b * Tlen;
    float lm = -INFINITY;
    for (int t = tid; t < Tlen; t += 256) lm = fmaxf(lm, aw[t]);
    s_red[tid] = lm; __syncthreads();
    for (int s = 128; s > 0; s >>= 1) {
        if (tid < s) s_red[tid] = fmaxf(s_red[tid], s_red[tid + s]);
        __syncthreads();
    }
    if (tid == 0) {
        g_invmax[b] = 1.f / fmaxf(s_red[0], 1e-6f);
        if (b == 0) {
            float bet = beta_ptr[0];
            g_bp[0] = (bet > 20.f) ? bet : log1pf(expf(bet));
        }
    }
}

// -------------------- Kernel 2: finalize (alpha + context) ------------------
__global__ void __launch_bounds__(256)
finalize_kernel(float* __restrict__ out) {
    __shared__ float sS[16];
    __shared__ float sInv;
    int b = blockIdx.x, tid = threadIdx.x;
    if (tid < 16) sS[tid] = g_S1[b * 16 + tid];
    __syncthreads();
    if (tid == 0) {
        float z = 0.f;
        #pragma unroll
        for (int j = 0; j < 16; j++) z += sS[j];
        sInv = 1.f / z;
    }
    __syncthreads();
    float inv = sInv;

    float* alpha_out = out + Bsz * Hdim + (size_t)b * Tlen;
    const float* ee = g_expE + (size_t)b * Tlen;
    for (int t = tid; t < Tlen; t += 256)
        alpha_out[t] = ee[t] * inv;

    if (tid < 128) {
        float c = 0.f;
        #pragma unroll
        for (int j = 0; j < 16; j++)
            c += g_ctx_part[((size_t)b * 16 + j) * 128 + tid];
        out[(size_t)b * Hdim + tid] = c * inv;
    }
}

// ---------------------------- launcher --------------------------------------
extern "C" void kernel_launch(void* const* d_in, const int* in_sizes, int n_in,
                              void* d_out, int out_size) {
    (void)in_sizes; (void)n_in; (void)out_size;
    const float* Hp   = (const float*)d_in[0];
    const float* Hd   = (const float*)d_in[1];
    const float* accw = (const float*)d_in[2];
    const float* Wh   = (const float*)d_in[3];
    const float* Wd   = (const float*)d_in[4];
    const float* Wa   = (const float*)d_in[5];
    const float* ba   = (const float*)d_in[6];
    const float* beta = (const float*)d_in[7];
    float* out = (float*)d_out;

    cudaFuncSetAttribute(energy_kernel, cudaFuncAttributeMaxDynamicSharedMemorySize, SMEM1);
    premax_kernel<<<Bsz, 256>>>(accw, beta);
    energy_kernel<<<GRID1, THR1, SMEM1>>>(Hp, Hd, accw, Wh, Wd, Wa, ba);
    finalize_kernel<<<Bsz, 256>>>(out);
}

// round 16
// speedup vs baseline: 1.1325x; 1.0679x over previous
#include <cuda_runtime.h>
#include <cuda_bf16.h>
#include <cuda_fp16.h>
#include <cstdint>
#include <math.h>

// ----------------------------------------------------------------------------
// B=128, T=2048, H=128
//   z = tanh(Hp @ Wh^T + Hd @ Wd^T); energy = z @ Wa + ba
//   alpha = softmax_T(energy * (1 + softplus(beta)*acc_w/max(acc_w)))
//   context = sum_t alpha * Hp
// Output: [context (B*H) | alpha (B*T)] fp32
//
// sm_103 (non-'a') ptxas: tcgen05 unavailable -> legacy mma.sync (HMMA).
// Single-term fp16 MMA, fp32 accum. Context fused into the energy epilogue.
// acc_w row-max computed INSIDE the energy kernel (CTA b<128 owns batch b,
// flag + fence publish; consumers poll during the pass-2 MMA shadow).
// ----------------------------------------------------------------------------

static constexpr int Bsz = 128, Tlen = 2048, Hdim = 128;
static constexpr int NTILES = Bsz * Tlen / 128;   // 2048 tiles of 128 tokens
static constexpr int GRID1  = 152;                // persistent CTAs (GB300 SMs)
static constexpr int THR1   = 512;                // 16 warps

__device__ float g_expE[Bsz * Tlen];              // exp(scaled energy)
__device__ float g_S1[NTILES];                    // per-tile sum of exp
__device__ float g_ctx_part[NTILES * Hdim];       // per-tile exp-weighted Hp sums
__device__ float g_invmax[Bsz];                   // 1/clip(max(acc_w),1e-6)
__device__ int   g_flag[Bsz];                     // invmax published flags

// ---------------------------- helpers ---------------------------------------
__device__ __forceinline__ uint32_t smem_u32(const void* p) {
    uint32_t a;
    asm("{ .reg .u64 t; cvta.to.shared.u64 t, %1; cvt.u32.u64 %0, t; }"
        : "=r"(a) : "l"(p));
    return a;
}

__device__ __forceinline__ void ldsm_x4(uint32_t* r, uint32_t addr) {
    asm volatile("ldmatrix.sync.aligned.m8n8.x4.shared.b16 {%0,%1,%2,%3}, [%4];"
                 : "=r"(r[0]), "=r"(r[1]), "=r"(r[2]), "=r"(r[3]) : "r"(addr));
}

__device__ __forceinline__ void ldsm_x2_trans(uint32_t* r, uint32_t addr) {
    asm volatile("ldmatrix.sync.aligned.m8n8.x2.trans.shared.b16 {%0,%1}, [%2];"
                 : "=r"(r[0]), "=r"(r[1]) : "r"(addr));
}

__device__ __forceinline__ void mma16816(float* d, const uint32_t* a,
                                         uint32_t b0, uint32_t b1) {
    asm volatile("mma.sync.aligned.m16n8k16.row.col.f32.f16.f16.f32 "
                 "{%0,%1,%2,%3}, {%4,%5,%6,%7}, {%8,%9}, {%0,%1,%2,%3};"
                 : "+f"(d[0]), "+f"(d[1]), "+f"(d[2]), "+f"(d[3])
                 : "r"(a[0]), "r"(a[1]), "r"(a[2]), "r"(a[3]), "r"(b0), "r"(b1));
}

__device__ __forceinline__ float tanh_approx(float x) {
    float y;
    asm("tanh.approx.f32 %0, %1;" : "=f"(y) : "f"(x));
    return y;
}

__device__ __forceinline__ void cp_async16(uint32_t saddr, const void* g) {
    asm volatile("cp.async.cg.shared.global [%0], [%1], 16;"
                 :: "r"(saddr), "l"(g) : "memory");
}
#define CP_COMMIT() asm volatile("cp.async.commit_group;" ::: "memory")
#define CP_WAIT0()  asm volatile("cp.async.wait_group 0;" ::: "memory")

// ---------------------------- SMEM layout -----------------------------------
static constexpr int PITCH_B  = 272;                 // 4-bank rotation per row
static constexpr int TILE_B   = 128 * PITCH_B;       // 34816 B
static constexpr int SM_AH0   = 0;                   // Hp tile (fp16)
static constexpr int SM_AH1   = SM_AH0 + TILE_B;     // Hd tile (fp16)
static constexpr int SM_WH    = SM_AH1 + TILE_B;     // Wh (fp16)
static constexpr int SM_WD    = SM_WH + TILE_B;      // Wd (fp16)
static constexpr int SM_STAGE = SM_WD + TILE_B;      // raw fp32 128x128
static constexpr int SM_WA    = SM_STAGE + 65536;    // 204800: Wa 128 fp32
static constexpr int SM_PART  = SM_WA + 512;         // 205312: 4x128 fp32
static constexpr int SM_EXPA  = SM_PART + 2048;      // 207360: 16x136 fp16 A strip
static constexpr int SM_RED   = SM_EXPA + 16 * PITCH_B;  // 211712: 16 fp32 + sInv
static constexpr int SMEM1    = SM_RED + 128;        // 211840 B

// Each thread owns 8 float4s of the stage: fi = wid*256 + k*32 + lane, k=0..7.
__device__ __forceinline__ void prefetch_own(uint32_t sb, const float* __restrict__ src,
                                             int fbase) {
    #pragma unroll
    for (int k = 0; k < 8; k++) {
        int fi = fbase + k * 32;
        cp_async16(sb + SM_STAGE + (uint32_t)fi * 16, src + (size_t)fi * 4);
    }
    CP_COMMIT();
}

__device__ __forceinline__ void convert_one(char* smem, int dst, int fi,
                                            const float4* stg) {
    float4 v = stg[fi];
    int row = fi >> 5, c = fi & 31;
    __half2 h0 = __floats2half2_rn(v.x, v.y);
    __half2 h1 = __floats2half2_rn(v.z, v.w);
    *(uint2*)(smem + dst + (uint32_t)row * PITCH_B + (uint32_t)c * 8) =
        make_uint2(*(const uint32_t*)&h0, *(const uint32_t*)&h1);
}

// One GEMM pass: D += AH(aBase) @ W(wBase)^T. Optionally convert the stage
// into cvtDst (starting at k2==CVT_START) and prefetch pf into the stage.
template <bool CVT, bool PF, int CVT_START>
__device__ __forceinline__ void pass_ic(char* smem, uint32_t sb,
                                        uint32_t aBase, uint32_t wBase, int cvtDst,
                                        const float* __restrict__ pf, int fbase,
                                        int lane, int wm, int wn, float d[2][4][4]) {
    uint32_t arow = (uint32_t)(wm * 32 + (lane & 15));
    uint32_t acol = (uint32_t)((lane >> 4) * 8);
    uint32_t brow = (uint32_t)(wn * 32 + (lane & 7));
    uint32_t bcol = (uint32_t)((lane >> 3) * 8);
    const float4* stg = (const float4*)(smem + SM_STAGE);
    constexpr int PER = 8 / (4 - CVT_START);   // converts per k2 step
    #pragma unroll
    for (int k2 = 0; k2 < 4; k2++) {
        uint32_t k0 = (uint32_t)(k2 * 32);
        uint32_t a[2][2][4];
        #pragma unroll
        for (int mt = 0; mt < 2; mt++)
            #pragma unroll
            for (int ks = 0; ks < 2; ks++)
                ldsm_x4(a[mt][ks],
                        aBase + (arow + mt * 16) * PITCH_B
                              + (k0 + ks * 16 + acol) * 2);
        #pragma unroll
        for (int nt = 0; nt < 4; nt++) {
            uint32_t b[4];
            ldsm_x4(b, wBase + (brow + nt * 8) * PITCH_B + (k0 + bcol) * 2);
            mma16816(d[0][nt], a[0][0], b[0], b[1]);
            mma16816(d[0][nt], a[0][1], b[2], b[3]);
            mma16816(d[1][nt], a[1][0], b[0], b[1]);
            mma16816(d[1][nt], a[1][1], b[2], b[3]);
        }
        if (CVT && k2 >= CVT_START) {
            if (k2 == CVT_START) CP_WAIT0();
            #pragma unroll
            for (int j = 0; j < PER; j++)
                convert_one(smem, cvtDst, fbase + ((k2 - CVT_START) * PER + j) * 32, stg);
        }
    }
    if (PF) prefetch_own(sb, pf, fbase);
}

__global__ void __launch_bounds__(THR1, 1)
energy_kernel(const float* __restrict__ Hp, const float* __restrict__ Hd,
              const float* __restrict__ accw,
              const float* __restrict__ Wh, const float* __restrict__ Wd,
              const float* __restrict__ Wa, const float* __restrict__ ba_ptr,
              const float* __restrict__ beta_ptr) {
    extern __shared__ char smem[];
    uint32_t sb = smem_u32(smem);
    const int tid = threadIdx.x;
    const int wid = tid >> 5, lane = tid & 31;
    const int wm  = wid >> 2, wn = wid & 3;
    const int g   = lane >> 2, t = lane & 3;
    const int fbase = wid * 256 + lane;
    float* sPart = (float*)(smem + SM_PART);
    float* sRed  = (float*)(smem + SM_RED);
    float* sInvF = (float*)(smem + SM_RED + 64);
    const float* sWa = (const float*)(smem + SM_WA);
    __half* sExpRow = (__half*)(smem + SM_EXPA);   // row 0 of A strip

    // ---- inline premax: CTA b<128 publishes 1/clip(max(acc_w[b,:])) ----
    if (blockIdx.x < Bsz) {
        const float* aw = accw + (size_t)blockIdx.x * Tlen;
        float m = -INFINITY;
        #pragma unroll
        for (int k = 0; k < 4; k++) m = fmaxf(m, aw[tid + 512 * k]);
        #pragma unroll
        for (int o = 16; o > 0; o >>= 1)
            m = fmaxf(m, __shfl_xor_sync(0xFFFFFFFFu, m, o));
        if (lane == 0) sRed[wid] = m;
        __syncthreads();
        if (tid == 0) {
            float mm = sRed[0];
            #pragma unroll
            for (int j = 1; j < 16; j++) mm = fmaxf(mm, sRed[j]);
            g_invmax[blockIdx.x] = 1.f / fmaxf(mm, 1e-6f);
            __threadfence();
            atomicExch(&g_flag[blockIdx.x], 1);
        }
        __syncthreads();
    }

    // one-time: weights fp32 -> fp16 tiles; zero the 16-row exp A strip
    for (int idx = tid; idx < 8192; idx += THR1) {
        int o = idx >> 6, h = (idx & 63) * 2;
        uint32_t off = (uint32_t)o * PITCH_B + (uint32_t)h * 2;
        float2 a = *(const float2*)(Wh + o * 128 + h);
        float2 b = *(const float2*)(Wd + o * 128 + h);
        __half2 ah = __floats2half2_rn(a.x, a.y);
        __half2 bh = __floats2half2_rn(b.x, b.y);
        *(uint32_t*)(smem + SM_WH + off) = *(const uint32_t*)&ah;
        *(uint32_t*)(smem + SM_WD + off) = *(const uint32_t*)&bh;
    }
    for (int idx = tid; idx < 16 * PITCH_B / 4; idx += THR1)
        ((uint32_t*)(smem + SM_EXPA))[idx] = 0;
    if (tid < 128) ((float*)(smem + SM_WA))[tid] = Wa[tid];
    const float ba = ba_ptr[0];
    const float betav = beta_ptr[0];
    const float bp = (betav > 20.f) ? betav : log1pf(expf(betav));

    // prologue: stage <- Hd[tile0]; convert -> AH1; stage <- Hp[tile0]
    const int tile0 = blockIdx.x;
    {
        const float4* stg = (const float4*)(smem + SM_STAGE);
        prefetch_own(sb, Hd + (size_t)tile0 * 16384, fbase);
        CP_WAIT0();
        #pragma unroll
        for (int k = 0; k < 8; k++)
            convert_one(smem, SM_AH1, fbase + k * 32, stg);
        prefetch_own(sb, Hp + (size_t)tile0 * 16384, fbase);
    }
    __syncthreads();   // weights + AH1 visible

    for (int tile = tile0; tile < NTILES; tile += GRID1) {
        size_t nbase = (size_t)(tile + GRID1) * 16384;
        const bool hasNext = (tile + GRID1) < NTILES;

        float d[2][4][4];
        #pragma unroll
        for (int mt = 0; mt < 2; mt++)
            #pragma unroll
            for (int nt = 0; nt < 4; nt++)
                #pragma unroll
                for (int j = 0; j < 4; j++) d[mt][nt][j] = 0.f;

        // pass 1: MMA(Hd_i @ Wd, A=AH1) | convert Hp_i -> AH0 | prefetch Hd_{i+1}
        if (hasNext)
            pass_ic<true, true, 0>(smem, sb, sb + SM_AH1, sb + SM_WD, SM_AH0,
                                   Hd + nbase, fbase, lane, wm, wn, d);
        else
            pass_ic<true, false, 0>(smem, sb, sb + SM_AH1, sb + SM_WD, SM_AH0,
                                    nullptr, fbase, lane, wm, wn, d);
        __syncthreads();   // AH0 (Hp_i) ready; AH1 reads done

        // fetch invmax[bb] during the pass-2 MMA shadow (flag poll, rare spin)
        if (tid == 0) {
            int bb = tile >> 4;
            volatile int* fl = g_flag + bb;
            float iv;
            if (*fl != 0) {
                __threadfence();
                iv = g_invmax[bb];
            } else {
                int it = 0;
                while (*fl == 0 && ++it < (1 << 22)) {}
                if (*fl != 0) {
                    __threadfence();
                    iv = g_invmax[bb];
                } else {
                    // deadlock-proof fallback: recompute serially
                    const float4* awp = (const float4*)(accw + (size_t)bb * Tlen);
                    float mm = 1e-6f;
                    #pragma unroll 8
                    for (int i = 0; i < 512; i++) {
                        float4 v = awp[i];
                        mm = fmaxf(mm, fmaxf(fmaxf(v.x, v.y), fmaxf(v.z, v.w)));
                    }
                    iv = 1.f / mm;
                }
            }
            *sInvF = iv;
        }

        // pass 2: MMA(Hp_i @ Wh, A=AH0) | convert Hd_{i+1} -> AH1 (late) | pf Hp_{i+1}
        if (hasNext)
            pass_ic<true, true, 2>(smem, sb, sb + SM_AH0, sb + SM_WH, SM_AH1,
                                   Hp + nbase, fbase, lane, wm, wn, d);
        else
            pass_ic<false, false, 2>(smem, sb, sb + SM_AH0, sb + SM_WH, SM_AH1,
                                     nullptr, fbase, lane, wm, wn, d);

        // ---- epilogue part 1: per-token energy -> w = exp(scaled energy) ----
        float e[2][2] = {{0.f, 0.f}, {0.f, 0.f}};
        #pragma unroll
        for (int nt = 0; nt < 4; nt++) {
            int n = wn * 32 + nt * 8 + 2 * t;
            float wa0 = sWa[n], wa1 = sWa[n + 1];
            #pragma unroll
            for (int mt = 0; mt < 2; mt++) {
                e[mt][0] += wa0 * tanh_approx(d[mt][nt][0])
                          + wa1 * tanh_approx(d[mt][nt][1]);
                e[mt][1] += wa0 * tanh_approx(d[mt][nt][2])
                          + wa1 * tanh_approx(d[mt][nt][3]);
            }
        }
        #pragma unroll
        for (int mt = 0; mt < 2; mt++)
            #pragma unroll
            for (int r = 0; r < 2; r++) {
                e[mt][r] += __shfl_xor_sync(0xFFFFFFFFu, e[mt][r], 1);
                e[mt][r] += __shfl_xor_sync(0xFFFFFFFFu, e[mt][r], 2);
            }
        if (t == 0) {
            #pragma unroll
            for (int mt = 0; mt < 2; mt++) {
                int row = wm * 32 + mt * 16 + g;
                sPart[wn * 128 + row]     = e[mt][0];
                sPart[wn * 128 + row + 8] = e[mt][1];
            }
        }
        __syncthreads();   // sPart + sInvF complete

        if (tid < 128) {
            float et = sPart[tid] + sPart[128 + tid] + sPart[256 + tid]
                     + sPart[384 + tid] + ba;
            float aw = accw[(size_t)tile * 128 + tid];
            float sc = 1.f + bp * (aw * (*sInvF));
            float w = expf(et * sc);                 // bounded arg
            g_expE[(size_t)tile * 128 + tid] = w;
            sExpRow[tid] = __float2half_rn(w);
            // per-warp sum of w (4 full warps)
            float s = w;
            #pragma unroll
            for (int o = 16; o > 0; o >>= 1)
                s += __shfl_xor_sync(0xFFFFFFFFu, s, o);
            if (lane == 0) sRed[wid] = s;
        }
        __syncthreads();   // sExpRow + sRed ready
        if (tid == 0)
            g_S1[tile] = sRed[0] + sRed[1] + sRed[2] + sRed[3];

        // ---- epilogue part 2: context partial C[h] = sum_t w_t * Hp[t][h] ----
        {
            float dc[4] = {0.f, 0.f, 0.f, 0.f};
            uint32_t h0 = (uint32_t)(wid * 8);
            #pragma unroll
            for (int kk = 0; kk < 8; kk++) {
                uint32_t areg[4];
                ldsm_x4(areg, sb + SM_EXPA + (uint32_t)(lane & 15) * PITCH_B
                              + (uint32_t)(kk * 16 + (lane >> 4) * 8) * 2);
                uint32_t breg[2];
                ldsm_x2_trans(breg, sb + SM_AH0
                              + (uint32_t)(kk * 16 + (lane & 15)) * PITCH_B + h0 * 2);
                mma16816(dc, areg, breg[0], breg[1]);
            }
            if ((lane >> 2) == 0) {   // row 0 of M16 lives in lanes 0-3 (d0,d1)
                int h = (int)h0 + (lane & 3) * 2;
                g_ctx_part[(size_t)tile * 128 + h]     = dc[0];
                g_ctx_part[(size_t)tile * 128 + h + 1] = dc[1];
            }
        }
        __syncthreads();   // AH0/sExpRow/sInvF reads done before next overwrite
    }
}

// -------------------- Kernel 2: finalize (alpha + context), 4 CTAs/batch ----
__global__ void __launch_bounds__(512)
finalize_kernel(float* __restrict__ out) {
    __shared__ float sS[16];
    __shared__ float sInv;
    int b = blockIdx.x >> 2, sub = blockIdx.x & 3;
    int tid = threadIdx.x;
    if (tid < 16) sS[tid] = g_S1[b * 16 + tid];
    __syncthreads();
    if (tid == 0) {
        float z = 0.f;
        #pragma unroll
        for (int j = 0; j < 16; j++) z += sS[j];
        sInv = 1.f / z;
    }
    __syncthreads();
    float inv = sInv;

    int t = sub * 512 + tid;
    out[Bsz * Hdim + (size_t)b * Tlen + t] = g_expE[(size_t)b * Tlen + t] * inv;

    if (sub == 0 && tid < 128) {
        float c = 0.f;
        #pragma unroll
        for (int j = 0; j < 16; j++)
            c += g_ctx_part[((size_t)b * 16 + j) * 128 + tid];
        out[(size_t)b * Hdim + tid] = c * inv;
    }
}

// ---------------------------- launcher --------------------------------------
extern "C" void kernel_launch(void* const* d_in, const int* in_sizes, int n_in,
                              void* d_out, int out_size) {
    (void)in_sizes; (void)n_in; (void)out_size;
    const float* Hp   = (const float*)d_in[0];
    const float* Hd   = (const float*)d_in[1];
    const float* accw = (const float*)d_in[2];
    const float* Wh   = (const float*)d_in[3];
    const float* Wd   = (const float*)d_in[4];
    const float* Wa   = (const float*)d_in[5];
    const float* ba   = (const float*)d_in[6];
    const float* beta = (const float*)d_in[7];
    float* out = (float*)d_out;

    cudaFuncSetAttribute(energy_kernel, cudaFuncAttributeMaxDynamicSharedMemorySize, SMEM1);
    energy_kernel<<<GRID1, THR1, SMEM1>>>(Hp, Hd, accw, Wh, Wd, Wa, ba, beta);
    finalize_kernel<<<Bsz * 4, 512>>>(out);
}